// round 7
// baseline (speedup 1.0000x reference)
#include <cuda_runtime.h>
#include <cuda_bf16.h>
#include <math.h>
#include <stdint.h>

#define NB    2048
#define NBITS 64
#define NH    512
#define NHV   256

__device__ float g_sp[NB * NH];
__device__ float g_vs[NB * NHV];
__device__ __nv_bfloat16 g_w2bf[NH * NH];     // W2^T bf16  [n][k]
__device__ __nv_bfloat16 g_w3bf[NBITS * NH];  // W3^T bf16  [n3][k]

__device__ __forceinline__ uint32_t smem_u32(const void* p) {
    uint32_t a;
    asm("{ .reg .u64 t; cvta.to.shared.u64 t, %1; cvt.u32.u64 %0, t; }"
        : "=r"(a) : "l"(p));
    return a;
}
__device__ __forceinline__ uint32_t pack_bf16x2(float lo, float hi) {
    uint32_t r;
    asm("cvt.rn.bf16x2.f32 %0, %1, %2;" : "=r"(r) : "f"(hi), "f"(lo));
    return r;
}
__device__ __forceinline__ void cp16(uint32_t dst, const void* src) {
    asm volatile("cp.async.cg.shared.global [%0], [%1], 16;"
                 :: "r"(dst), "l"(src) : "memory");
}
__device__ __forceinline__ void mma_bf16(float* c, const uint32_t* a,
                                         uint32_t b0, uint32_t b1) {
    asm volatile("mma.sync.aligned.m16n8k16.row.col.f32.bf16.bf16.f32 "
                 "{%0,%1,%2,%3}, {%4,%5,%6,%7}, {%8,%9}, {%0,%1,%2,%3};"
                 : "+f"(c[0]), "+f"(c[1]), "+f"(c[2]), "+f"(c[3])
                 : "r"(a[0]), "r"(a[1]), "r"(a[2]), "r"(a[3]),
                   "r"(b0), "r"(b1));
}
__device__ __forceinline__ void ldm_x4(uint32_t* r, uint32_t addr) {
    asm volatile("ldmatrix.sync.aligned.m8n8.x4.shared.b16 {%0,%1,%2,%3}, [%4];"
                 : "=r"(r[0]), "=r"(r[1]), "=r"(r[2]), "=r"(r[3]) : "r"(addr));
}

#define H1_OFF   0
#define W2_OFF   133120
#define W2_TILE  34816
#define W3_OFF   202752
#define B2_OFF   220160
#define B3_OFF   222208
#define AB_OFF   222464
#define VS_OFF   222976
#define VW2_OFF  225024
#define SM_TOTAL 226048

__global__ void prep_w2_kernel(const float* __restrict__ ix_w2) {
    int idx = blockIdx.x * 256 + threadIdx.x;
    int n = idx >> 9, k = idx & 511;
    g_w2bf[n * NH + k] = __float2bfloat16(ix_w2[k * NH + n]);
}
__global__ void prep_w3_kernel(const float* __restrict__ ix_w3) {
    int idx = blockIdx.x * 256 + threadIdx.x;
    int n3 = idx >> 9, k = idx & 511;
    g_w3bf[n3 * NH + k] = __float2bfloat16(ix_w3[k * NBITS + n3]);
}

__global__ __launch_bounds__(256) void shift_net_kernel(
    const float* __restrict__ shift_bits,
    const float* __restrict__ sd_w1, const float* __restrict__ sd_b1,
    const float* __restrict__ sd_w2, const float* __restrict__ sd_b2,
    const float* __restrict__ sd_w3, const float* __restrict__ sd_b3,
    const float* __restrict__ ix_w1, const float* __restrict__ v_w1)
{
    const int ROWS = 8;
    __shared__ float xs[ROWS][NBITS];
    __shared__ float hs[ROWS][NH];
    __shared__ float gs[ROWS][NH];
    __shared__ float lgs[ROWS][NBITS];
    __shared__ float sms[ROWS][NBITS];

    const int t  = threadIdx.x;
    const int b0 = blockIdx.x * ROWS;

    for (int idx = t; idx < ROWS * NBITS; idx += 256) {
        int r = idx >> 6, k = idx & 63;
        xs[r][k] = shift_bits[(b0 + r) * NBITS + k];
    }
    __syncthreads();

    {
        const int j0 = t, j1 = t + 256;
        float a0[ROWS], a1[ROWS];
        #pragma unroll
        for (int r = 0; r < ROWS; r++) { a0[r] = 0.f; a1[r] = 0.f; }
        for (int k = 0; k < NBITS; k++) {
            float w0 = sd_w1[k * NH + j0];
            float w1 = sd_w1[k * NH + j1];
            #pragma unroll
            for (int r = 0; r < ROWS; r++) {
                a0[r] = fmaf(xs[r][k], w0, a0[r]);
                a1[r] = fmaf(xs[r][k], w1, a1[r]);
            }
        }
        float bb0 = sd_b1[j0], bb1 = sd_b1[j1];
        #pragma unroll
        for (int r = 0; r < ROWS; r++) {
            hs[r][j0] = fmaxf(a0[r] + bb0, 0.f);
            hs[r][j1] = fmaxf(a1[r] + bb1, 0.f);
        }
    }
    __syncthreads();

    {
        const int j0 = t, j1 = t + 256;
        float a0[ROWS], a1[ROWS];
        #pragma unroll
        for (int r = 0; r < ROWS; r++) { a0[r] = 0.f; a1[r] = 0.f; }
        for (int k = 0; k < NH; k++) {
            float w0 = sd_w2[k * NH + j0];
            float w1 = sd_w2[k * NH + j1];
            #pragma unroll
            for (int r = 0; r < ROWS; r++) {
                a0[r] = fmaf(hs[r][k], w0, a0[r]);
                a1[r] = fmaf(hs[r][k], w1, a1[r]);
            }
        }
        float bb0 = sd_b2[j0], bb1 = sd_b2[j1];
        #pragma unroll
        for (int r = 0; r < ROWS; r++) {
            gs[r][j0] = fmaxf(a0[r] + bb0, 0.f);
            gs[r][j1] = fmaxf(a1[r] + bb1, 0.f);
        }
    }
    __syncthreads();

    #pragma unroll
    for (int p = 0; p < 2; p++) {
        int idx = t + p * 256;
        int r = idx >> 6, j = idx & 63;
        float acc = 0.f;
        for (int k = 0; k < NH; k++)
            acc = fmaf(gs[r][k], sd_w3[k * NBITS + j], acc);
        lgs[r][j] = acc + sd_b3[j];
    }
    __syncthreads();

    {
        int w = t >> 5, l = t & 31;
        float v0 = lgs[w][l], v1 = lgs[w][l + 32];
        float m = fmaxf(v0, v1);
        #pragma unroll
        for (int o = 16; o > 0; o >>= 1) m = fmaxf(m, __shfl_xor_sync(0xffffffffu, m, o));
        float e0 = expf(v0 - m), e1 = expf(v1 - m);
        float s = e0 + e1;
        #pragma unroll
        for (int o = 16; o > 0; o >>= 1) s += __shfl_xor_sync(0xffffffffu, s, o);
        float inv = 1.f / s;
        sms[w][l] = e0 * inv;
        sms[w][l + 32] = e1 * inv;
    }
    __syncthreads();

    {
        const int j0 = t, j1 = t + 256;
        float a0[ROWS], a1[ROWS];
        #pragma unroll
        for (int r = 0; r < ROWS; r++) { a0[r] = 0.f; a1[r] = 0.f; }
        for (int k = 0; k < NBITS; k++) {
            float w0 = ix_w1[(NBITS + k) * NH + j0];
            float w1 = ix_w1[(NBITS + k) * NH + j1];
            #pragma unroll
            for (int r = 0; r < ROWS; r++) {
                a0[r] = fmaf(sms[r][k], w0, a0[r]);
                a1[r] = fmaf(sms[r][k], w1, a1[r]);
            }
        }
        #pragma unroll
        for (int r = 0; r < ROWS; r++) {
            g_sp[(b0 + r) * NH + j0] = a0[r];
            g_sp[(b0 + r) * NH + j1] = a1[r];
        }
    }

    {
        const int j = t;
        float a[ROWS];
        #pragma unroll
        for (int r = 0; r < ROWS; r++) a[r] = 0.f;
        for (int k = 0; k < NBITS; k++) {
            float w = v_w1[(NBITS + k) * NHV + j];
            #pragma unroll
            for (int r = 0; r < ROWS; r++)
                a[r] = fmaf(sms[r][k], w, a[r]);
        }
        #pragma unroll
        for (int r = 0; r < ROWS; r++)
            g_vs[(b0 + r) * NHV + j] = a[r];
    }
}

__global__ __launch_bounds__(256, 1) void main_mma_kernel(
    const float* __restrict__ a_bits,
    const float* __restrict__ ix_w1, const float* __restrict__ ix_b1,
    const float* __restrict__ ix_b2, const float* __restrict__ ix_b3,
    const float* __restrict__ v_w1,  const float* __restrict__ v_b1,
    const float* __restrict__ v_w2,  const float* __restrict__ v_b2,
    float* __restrict__ out)
{
    extern __shared__ char bp[];
    float* b2s  = (float*)(bp + B2_OFF);
    float* b3s  = (float*)(bp + B3_OFF);
    float* ab_s = (float*)(bp + AB_OFF);
    float* vs_s = (float*)(bp + VS_OFF);
    float* vw2s = (float*)(bp + VW2_OFF);

    const int t    = threadIdx.x;
    const int lane = t & 31, w = t >> 5;
    const int g = lane >> 2, tg = lane & 3;
    const int pair = blockIdx.x;
    const int m0 = w * 16;

    const uint32_t smb = smem_u32(bp);

    {   // prologue: W2 chunk 0
        const __nv_bfloat16* src = g_w2bf;
        #pragma unroll
        for (int i = 0; i < 8; i++) {
            int idx = t + i * 256;
            int row = idx >> 4, c16 = idx & 15;
            cp16(smb + W2_OFF + row * 272 + c16 * 16, src + row * NH + c16 * 8);
        }
        asm volatile("cp.async.commit_group;" ::: "memory");
    }

    for (int i = t; i < NH; i += 256) {
        b2s[i]  = ix_b2[i];
        vs_s[i] = g_vs[(2 * pair + (i >> 8)) * NHV + (i & 255)] + v_b1[i & 255];
    }
    vw2s[t] = v_w2[t];
    if (t < NBITS) b3s[t] = ix_b3[t];
    if (t < 128)   ab_s[t] = a_bits[(2 * pair + (t >> 6)) * NBITS + (t & 63)];

    #pragma unroll 4
    for (int i = 0; i < 64; i++) {
        int idx = t + i * 256;
        int m = idx >> 7, q = idx & 127;
        int k = q * 4;
        float4 p  = *(const float4*)(ix_w1 + (m & 63) * NH + k);
        float4 s  = *(const float4*)(g_sp + (2 * pair + (m >> 6)) * NH + k);
        float4 bb = *(const float4*)(ix_b1 + k);
        uint32_t lo = pack_bf16x2(fmaxf(p.x + s.x + bb.x, 0.f),
                                  fmaxf(p.y + s.y + bb.y, 0.f));
        uint32_t hi = pack_bf16x2(fmaxf(p.z + s.z + bb.z, 0.f),
                                  fmaxf(p.w + s.w + bb.w, 0.f));
        *(uint2*)(bp + H1_OFF + m * 1040 + k * 2) = make_uint2(lo, hi);
    }

    float lg[8][4];
    #pragma unroll
    for (int i = 0; i < 8; i++)
        #pragma unroll
        for (int j2 = 0; j2 < 4; j2++) lg[i][j2] = 0.f;

    float acc[16][4];

    const uint32_t h1a = smb + H1_OFF + (m0 + (lane & 15)) * 1040 + (lane >> 4) * 16;
    const uint32_t bfrag = (uint32_t)((lane & 7) * 272 + (lane >> 3) * 16);
    const uint32_t w3a = smb + W3_OFF + bfrag;

    for (int c = 0; c < 16; c++) {
        const int nb = c >> 2, kb = c & 3;
        const int next = c + 1;
        if (next < 16) {
            int nnb = next >> 2, nkb = next & 3;
            const __nv_bfloat16* src = g_w2bf + (nnb * 128) * NH + nkb * 128;
            uint32_t dstb = smb + W2_OFF + (next & 1) * W2_TILE;
            #pragma unroll
            for (int i = 0; i < 8; i++) {
                int idx = t + i * 256;
                int row = idx >> 4, c16 = idx & 15;
                cp16(dstb + row * 272 + c16 * 16, src + row * NH + c16 * 8);
            }
            if (nkb == 1) {
                const __nv_bfloat16* s3 = g_w3bf + nnb * 128;
                #pragma unroll
                for (int i = 0; i < 4; i++) {
                    int idx = t + i * 256;
                    int row = idx >> 4, c16 = idx & 15;
                    cp16(smb + W3_OFF + row * 272 + c16 * 16, s3 + row * NH + c16 * 8);
                }
            }
            asm volatile("cp.async.commit_group;" ::: "memory");
            asm volatile("cp.async.wait_group 1;" ::: "memory");
        } else {
            asm volatile("cp.async.wait_group 0;" ::: "memory");
        }
        __syncthreads();

        if (kb == 0) {
            #pragma unroll
            for (int i = 0; i < 16; i++) {
                acc[i][0] = 0.f; acc[i][1] = 0.f; acc[i][2] = 0.f; acc[i][3] = 0.f;
            }
        }

        uint32_t A[8][4];
        {
            const uint32_t abase = h1a + (uint32_t)(kb * 256);
            #pragma unroll
            for (int ks = 0; ks < 8; ks++) ldm_x4(A[ks], abase + ks * 32);
        }
        const uint32_t w2b = smb + W2_OFF + (c & 1) * W2_TILE + bfrag;
        #pragma unroll
        for (int nt = 0; nt < 16; nt++) {
            const uint32_t brow = w2b + nt * (8 * 272);
            #pragma unroll
            for (int ks2 = 0; ks2 < 4; ks2++) {
                uint32_t Bv[4];
                ldm_x4(Bv, brow + ks2 * 64);
                mma_bf16(acc[nt], A[2 * ks2],     Bv[0], Bv[1]);
                mma_bf16(acc[nt], A[2 * ks2 + 1], Bv[2], Bv[3]);
            }
        }

        if (kb == 3) {
            // GEMM2(nb): A2 from accs; B via ldmatrix (one x4 covers j, j+1).
            #pragma unroll
            for (int j = 0; j < 8; j += 2) {
                uint32_t Af0[4], Af1[4];
                #pragma unroll
                for (int jj = 0; jj < 2; jj++) {
                    uint32_t* Af = jj ? Af1 : Af0;
                    int jc = j + jj;
                    int n0a = nb * 128 + jc * 16 + tg * 2;
                    int n0b = n0a + 8;
                    float bA0 = b2s[n0a], bA1 = b2s[n0a + 1];
                    float bB0 = b2s[n0b], bB1 = b2s[n0b + 1];
                    Af[0] = pack_bf16x2(fmaxf(acc[2*jc  ][0] + bA0, 0.f),
                                        fmaxf(acc[2*jc  ][1] + bA1, 0.f));
                    Af[1] = pack_bf16x2(fmaxf(acc[2*jc  ][2] + bA0, 0.f),
                                        fmaxf(acc[2*jc  ][3] + bA1, 0.f));
                    Af[2] = pack_bf16x2(fmaxf(acc[2*jc+1][0] + bB0, 0.f),
                                        fmaxf(acc[2*jc+1][1] + bB1, 0.f));
                    Af[3] = pack_bf16x2(fmaxf(acc[2*jc+1][2] + bB0, 0.f),
                                        fmaxf(acc[2*jc+1][3] + bB1, 0.f));
                }
                #pragma unroll
                for (int nt3 = 0; nt3 < 8; nt3++) {
                    uint32_t Bv[4];
                    ldm_x4(Bv, w3a + nt3 * (8 * 272) + (j >> 1) * 64);
                    mma_bf16(lg[nt3], Af0, Bv[0], Bv[1]);
                    mma_bf16(lg[nt3], Af1, Bv[2], Bv[3]);
                }
            }
        }
        __syncthreads();
    }

    #pragma unroll
    for (int rr = 0; rr < 2; rr++) {
        const int r = m0 + g + rr * 8;
        const int o = rr * 2;
        float v[16];
        float mx = -1e30f;
        #pragma unroll
        for (int nt3 = 0; nt3 < 8; nt3++) {
            float x0 = lg[nt3][o]     + b3s[nt3 * 8 + tg * 2];
            float x1 = lg[nt3][o + 1] + b3s[nt3 * 8 + tg * 2 + 1];
            v[2 * nt3] = x0; v[2 * nt3 + 1] = x1;
            mx = fmaxf(mx, fmaxf(x0, x1));
        }
        mx = fmaxf(mx, __shfl_xor_sync(0xffffffffu, mx, 1));
        mx = fmaxf(mx, __shfl_xor_sync(0xffffffffu, mx, 2));

        const int bsel = r >> 6;
        const float* abr = ab_s + bsel * NBITS;
        float den = 0.f, num = 0.f;
        #pragma unroll
        for (int nt3 = 0; nt3 < 8; nt3++) {
            float e0 = expf(v[2 * nt3]     - mx);
            float e1 = expf(v[2 * nt3 + 1] - mx);
            den += e0 + e1;
            num += e0 * abr[nt3 * 8 + tg * 2] + e1 * abr[nt3 * 8 + tg * 2 + 1];
        }
        den += __shfl_xor_sync(0xffffffffu, den, 1);
        den += __shfl_xor_sync(0xffffffffu, den, 2);
        num += __shfl_xor_sync(0xffffffffu, num, 1);
        num += __shfl_xor_sync(0xffffffffu, num, 2);
        float pointed = num / den;

        const int R = r & 63;
        const float* vrow = v_w1 + R * NHV;
        const float* vsr  = vs_s + bsel * NHV;
        float acc2 = 0.f;
        #pragma unroll 8
        for (int jj = 0; jj < 64; jj++) {
            int j = jj * 4 + tg;
            float vh = fmaxf(vrow[j] + vsr[j], 0.f);
            acc2 = fmaf(vh, vw2s[j], acc2);
        }
        acc2 += __shfl_xor_sync(0xffffffffu, acc2, 1);
        acc2 += __shfl_xor_sync(0xffffffffu, acc2, 2);
        if (tg == 0) {
            float vlog = acc2 + v_b2[0];
            out[(2 * pair + bsel) * NBITS + R] =
                pointed * (1.f / (1.f + expf(-vlog)));
        }
    }
}

extern "C" void kernel_launch(void* const* d_in, const int* in_sizes, int n_in,
                              void* d_out, int out_size)
{
    const float* a_bits     = (const float*)d_in[0];
    const float* shift_bits = (const float*)d_in[1];
    const float* sd_w1 = (const float*)d_in[2];
    const float* sd_b1 = (const float*)d_in[3];
    const float* sd_w2 = (const float*)d_in[4];
    const float* sd_b2 = (const float*)d_in[5];
    const float* sd_w3 = (const float*)d_in[6];
    const float* sd_b3 = (const float*)d_in[7];
    const float* ix_w1 = (const float*)d_in[8];
    const float* ix_b1 = (const float*)d_in[9];
    const float* ix_w2 = (const float*)d_in[10];
    const float* ix_b2 = (const float*)d_in[11];
    const float* ix_w3 = (const float*)d_in[12];
    const float* ix_b3 = (const float*)d_in[13];
    const float* v_w1  = (const float*)d_in[14];
    const float* v_b1  = (const float*)d_in[15];
    const float* v_w2  = (const float*)d_in[16];
    const float* v_b2  = (const float*)d_in[17];
    float* out = (float*)d_out;

    cudaFuncSetAttribute(main_mma_kernel,
                         cudaFuncAttributeMaxDynamicSharedMemorySize, SM_TOTAL);

    prep_w2_kernel<<<1024, 256>>>(ix_w2);
    prep_w3_kernel<<<128, 256>>>(ix_w3);
    shift_net_kernel<<<NB / 8, 256>>>(shift_bits, sd_w1, sd_b1, sd_w2, sd_b2,
                                      sd_w3, sd_b3, ix_w1, v_w1);
    main_mma_kernel<<<NB / 2, 256, SM_TOTAL>>>(a_bits, ix_w1, ix_b1, ix_b2, ix_b3,
                                               v_w1, v_b1, v_w2, v_b2, out);
}

// round 8
// speedup vs baseline: 1.0156x; 1.0156x over previous
#include <cuda_runtime.h>
#include <cuda_bf16.h>
#include <math.h>
#include <stdint.h>

#define NB    2048
#define NBITS 64
#define NH    512
#define NHV   256

__device__ float g_sp[NB * NH];
__device__ float g_vs[NB * NHV];
__device__ __nv_bfloat16 g_w2bf[NH * NH];     // W2^T bf16  [n][k]
__device__ __nv_bfloat16 g_w3bf[NBITS * NH];  // W3^T bf16  [n3][k]

__device__ __forceinline__ uint32_t smem_u32(const void* p) {
    uint32_t a;
    asm("{ .reg .u64 t; cvta.to.shared.u64 t, %1; cvt.u32.u64 %0, t; }"
        : "=r"(a) : "l"(p));
    return a;
}
__device__ __forceinline__ uint32_t pack_bf16x2(float lo, float hi) {
    uint32_t r;
    asm("cvt.rn.bf16x2.f32 %0, %1, %2;" : "=r"(r) : "f"(hi), "f"(lo));
    return r;
}
__device__ __forceinline__ void cp16(uint32_t dst, const void* src) {
    asm volatile("cp.async.cg.shared.global [%0], [%1], 16;"
                 :: "r"(dst), "l"(src) : "memory");
}
__device__ __forceinline__ void mma_bf16(float* c, const uint32_t* a,
                                         uint32_t b0, uint32_t b1) {
    asm volatile("mma.sync.aligned.m16n8k16.row.col.f32.bf16.bf16.f32 "
                 "{%0,%1,%2,%3}, {%4,%5,%6,%7}, {%8,%9}, {%0,%1,%2,%3};"
                 : "+f"(c[0]), "+f"(c[1]), "+f"(c[2]), "+f"(c[3])
                 : "r"(a[0]), "r"(a[1]), "r"(a[2]), "r"(a[3]),
                   "r"(b0), "r"(b1));
}
__device__ __forceinline__ void ldm_x4(uint32_t* r, uint32_t addr) {
    asm volatile("ldmatrix.sync.aligned.m8n8.x4.shared.b16 {%0,%1,%2,%3}, [%4];"
                 : "=r"(r[0]), "=r"(r[1]), "=r"(r[2]), "=r"(r[3]) : "r"(addr));
}

#define H1_OFF   0         // 128 rows x 1040 B
#define W2_OFF   133120    // 2 x 34816 (tile: 128 n-rows x 272 B)
#define W2_TILE  34816
#define W3_OFF   202752    // 64 rows x 272 B
#define B2_OFF   220160
#define B3_OFF   222208
#define AB_OFF   222464
#define VS_OFF   222976
#define VW2_OFF  225024
#define SM_TOTAL 226048
// logits buffer after mainloop: reuse W2 buffer 0 (f32, stride 68)
#define LG_OFF   W2_OFF

__global__ void prep_w2_kernel(const float* __restrict__ ix_w2) {
    int idx = blockIdx.x * 256 + threadIdx.x;
    int n = idx >> 9, k = idx & 511;
    g_w2bf[n * NH + k] = __float2bfloat16(ix_w2[k * NH + n]);
}
__global__ void prep_w3_kernel(const float* __restrict__ ix_w3) {
    int idx = blockIdx.x * 256 + threadIdx.x;
    int n3 = idx >> 9, k = idx & 511;
    g_w3bf[n3 * NH + k] = __float2bfloat16(ix_w3[k * NBITS + n3]);
}

__global__ __launch_bounds__(256) void shift_net_kernel(
    const float* __restrict__ shift_bits,
    const float* __restrict__ sd_w1, const float* __restrict__ sd_b1,
    const float* __restrict__ sd_w2, const float* __restrict__ sd_b2,
    const float* __restrict__ sd_w3, const float* __restrict__ sd_b3,
    const float* __restrict__ ix_w1, const float* __restrict__ v_w1)
{
    const int ROWS = 8;
    __shared__ float xs[ROWS][NBITS];
    __shared__ float hs[ROWS][NH];
    __shared__ float gs[ROWS][NH];
    __shared__ float lgs[ROWS][NBITS];
    __shared__ float sms[ROWS][NBITS];

    const int t  = threadIdx.x;
    const int b0 = blockIdx.x * ROWS;

    for (int idx = t; idx < ROWS * NBITS; idx += 256) {
        int r = idx >> 6, k = idx & 63;
        xs[r][k] = shift_bits[(b0 + r) * NBITS + k];
    }
    __syncthreads();

    {
        const int j0 = t, j1 = t + 256;
        float a0[ROWS], a1[ROWS];
        #pragma unroll
        for (int r = 0; r < ROWS; r++) { a0[r] = 0.f; a1[r] = 0.f; }
        for (int k = 0; k < NBITS; k++) {
            float w0 = sd_w1[k * NH + j0];
            float w1 = sd_w1[k * NH + j1];
            #pragma unroll
            for (int r = 0; r < ROWS; r++) {
                a0[r] = fmaf(xs[r][k], w0, a0[r]);
                a1[r] = fmaf(xs[r][k], w1, a1[r]);
            }
        }
        float bb0 = sd_b1[j0], bb1 = sd_b1[j1];
        #pragma unroll
        for (int r = 0; r < ROWS; r++) {
            hs[r][j0] = fmaxf(a0[r] + bb0, 0.f);
            hs[r][j1] = fmaxf(a1[r] + bb1, 0.f);
        }
    }
    __syncthreads();

    {
        const int j0 = t, j1 = t + 256;
        float a0[ROWS], a1[ROWS];
        #pragma unroll
        for (int r = 0; r < ROWS; r++) { a0[r] = 0.f; a1[r] = 0.f; }
        for (int k = 0; k < NH; k++) {
            float w0 = sd_w2[k * NH + j0];
            float w1 = sd_w2[k * NH + j1];
            #pragma unroll
            for (int r = 0; r < ROWS; r++) {
                a0[r] = fmaf(hs[r][k], w0, a0[r]);
                a1[r] = fmaf(hs[r][k], w1, a1[r]);
            }
        }
        float bb0 = sd_b2[j0], bb1 = sd_b2[j1];
        #pragma unroll
        for (int r = 0; r < ROWS; r++) {
            gs[r][j0] = fmaxf(a0[r] + bb0, 0.f);
            gs[r][j1] = fmaxf(a1[r] + bb1, 0.f);
        }
    }
    __syncthreads();

    #pragma unroll
    for (int p = 0; p < 2; p++) {
        int idx = t + p * 256;
        int r = idx >> 6, j = idx & 63;
        float acc = 0.f;
        for (int k = 0; k < NH; k++)
            acc = fmaf(gs[r][k], sd_w3[k * NBITS + j], acc);
        lgs[r][j] = acc + sd_b3[j];
    }
    __syncthreads();

    {
        int w = t >> 5, l = t & 31;
        float v0 = lgs[w][l], v1 = lgs[w][l + 32];
        float m = fmaxf(v0, v1);
        #pragma unroll
        for (int o = 16; o > 0; o >>= 1) m = fmaxf(m, __shfl_xor_sync(0xffffffffu, m, o));
        float e0 = expf(v0 - m), e1 = expf(v1 - m);
        float s = e0 + e1;
        #pragma unroll
        for (int o = 16; o > 0; o >>= 1) s += __shfl_xor_sync(0xffffffffu, s, o);
        float inv = 1.f / s;
        sms[w][l] = e0 * inv;
        sms[w][l + 32] = e1 * inv;
    }
    __syncthreads();

    {
        const int j0 = t, j1 = t + 256;
        float a0[ROWS], a1[ROWS];
        #pragma unroll
        for (int r = 0; r < ROWS; r++) { a0[r] = 0.f; a1[r] = 0.f; }
        for (int k = 0; k < NBITS; k++) {
            float w0 = ix_w1[(NBITS + k) * NH + j0];
            float w1 = ix_w1[(NBITS + k) * NH + j1];
            #pragma unroll
            for (int r = 0; r < ROWS; r++) {
                a0[r] = fmaf(sms[r][k], w0, a0[r]);
                a1[r] = fmaf(sms[r][k], w1, a1[r]);
            }
        }
        #pragma unroll
        for (int r = 0; r < ROWS; r++) {
            g_sp[(b0 + r) * NH + j0] = a0[r];
            g_sp[(b0 + r) * NH + j1] = a1[r];
        }
    }

    {
        const int j = t;
        float a[ROWS];
        #pragma unroll
        for (int r = 0; r < ROWS; r++) a[r] = 0.f;
        for (int k = 0; k < NBITS; k++) {
            float w = v_w1[(NBITS + k) * NHV + j];
            #pragma unroll
            for (int r = 0; r < ROWS; r++)
                a[r] = fmaf(sms[r][k], w, a[r]);
        }
        #pragma unroll
        for (int r = 0; r < ROWS; r++)
            g_vs[(b0 + r) * NHV + j] = a[r];
    }
}

// ---------------------------------------------------------------------------
// Kernel 2: 512 threads / 16 warps. GEMM1 warp tile 16x64 (mg = w&7, ng = w>>3).
// GEMM2 via h2 bounce through the retired W2 buffer. Logits via smem.
// ---------------------------------------------------------------------------
__global__ __launch_bounds__(512) void main_mma_kernel(
    const float* __restrict__ a_bits,
    const float* __restrict__ ix_w1, const float* __restrict__ ix_b1,
    const float* __restrict__ ix_b2, const float* __restrict__ ix_b3,
    const float* __restrict__ v_w1,  const float* __restrict__ v_b1,
    const float* __restrict__ v_w2,  const float* __restrict__ v_b2,
    float* __restrict__ out)
{
    extern __shared__ char bp[];
    float* b2s  = (float*)(bp + B2_OFF);
    float* b3s  = (float*)(bp + B3_OFF);
    float* ab_s = (float*)(bp + AB_OFF);
    float* vs_s = (float*)(bp + VS_OFF);
    float* vw2s = (float*)(bp + VW2_OFF);

    const int t    = threadIdx.x;
    const int lane = t & 31, w = t >> 5;     // 16 warps
    const int g = lane >> 2, tg = lane & 3;
    const int mg = w & 7, ng = w >> 3;       // m-group 0..7, n-group 0..1
    const int m0 = mg * 16;
    const int n0 = ng * 64;                  // GEMM1 col base within 128-chunk
    const int pair = blockIdx.x;

    const uint32_t smb = smem_u32(bp);

    {   // prologue: W2 chunk 0
        const __nv_bfloat16* src = g_w2bf;
        #pragma unroll
        for (int i = 0; i < 4; i++) {
            int idx = t + i * 512;
            int row = idx >> 4, c16 = idx & 15;
            cp16(smb + W2_OFF + row * 272 + c16 * 16, src + row * NH + c16 * 8);
        }
        asm volatile("cp.async.commit_group;" ::: "memory");
    }

    for (int i = t; i < NH; i += 512) {
        b2s[i]  = ix_b2[i];
        vs_s[i] = g_vs[(2 * pair + (i >> 8)) * NHV + (i & 255)] + v_b1[i & 255];
    }
    if (t < 256) vw2s[t] = v_w2[t];
    if (t < NBITS) b3s[t] = ix_b3[t];
    if (t < 128)   ab_s[t] = a_bits[(2 * pair + (t >> 6)) * NBITS + (t & 63)];

    // h1 build: bf16 [128 rows][512 k], stride 1040 B
    #pragma unroll 4
    for (int i = 0; i < 32; i++) {
        int idx = t + i * 512;
        int m = idx >> 7, q = idx & 127;
        int k = q * 4;
        float4 p  = *(const float4*)(ix_w1 + (m & 63) * NH + k);
        float4 s  = *(const float4*)(g_sp + (2 * pair + (m >> 6)) * NH + k);
        float4 bb = *(const float4*)(ix_b1 + k);
        uint32_t lo = pack_bf16x2(fmaxf(p.x + s.x + bb.x, 0.f),
                                  fmaxf(p.y + s.y + bb.y, 0.f));
        uint32_t hi = pack_bf16x2(fmaxf(p.z + s.z + bb.z, 0.f),
                                  fmaxf(p.w + s.w + bb.w, 0.f));
        *(uint2*)(bp + H1_OFF + m * 1040 + k * 2) = make_uint2(lo, hi);
    }

    float lg[4][4];       // GEMM2: 16 rows x 32 cols per warp
    #pragma unroll
    for (int i = 0; i < 4; i++)
        #pragma unroll
        for (int j2 = 0; j2 < 4; j2++) lg[i][j2] = 0.f;

    float acc[8][4];      // GEMM1: 16 rows x 64 cols per warp

    const uint32_t h1a = smb + H1_OFF + (m0 + (lane & 15)) * 1040 + (lane >> 4) * 16;
    const uint32_t bfrag = (uint32_t)((lane & 7) * 272 + (lane >> 3) * 16);
    const uint32_t w3a = smb + W3_OFF + bfrag;
    const uint32_t a2frag = (uint32_t)((m0 + (lane & 15)) * 272 + (lane >> 4) * 16);

    for (int c = 0; c < 16; c++) {
        const int nb = c >> 2, kb = c & 3;
        const int next = c + 1;
        if (next < 16) {
            int nnb = next >> 2, nkb = next & 3;
            const __nv_bfloat16* src = g_w2bf + (nnb * 128) * NH + nkb * 128;
            uint32_t dstb = smb + W2_OFF + (next & 1) * W2_TILE;
            #pragma unroll
            for (int i = 0; i < 4; i++) {
                int idx = t + i * 512;
                int row = idx >> 4, c16 = idx & 15;
                cp16(dstb + row * 272 + c16 * 16, src + row * NH + c16 * 8);
            }
            if (nkb == 1) {
                const __nv_bfloat16* s3 = g_w3bf + nnb * 128;
                #pragma unroll
                for (int i = 0; i < 2; i++) {
                    int idx = t + i * 512;
                    int row = idx >> 4, c16 = idx & 15;
                    cp16(smb + W3_OFF + row * 272 + c16 * 16, s3 + row * NH + c16 * 8);
                }
            }
            asm volatile("cp.async.commit_group;" ::: "memory");
            asm volatile("cp.async.wait_group 1;" ::: "memory");
        } else {
            asm volatile("cp.async.wait_group 0;" ::: "memory");
        }
        __syncthreads();

        if (kb == 0) {
            #pragma unroll
            for (int i = 0; i < 8; i++) {
                acc[i][0] = 0.f; acc[i][1] = 0.f; acc[i][2] = 0.f; acc[i][3] = 0.f;
            }
        }

        // A fragments for this K-slab
        uint32_t A[8][4];
        {
            const uint32_t abase = h1a + (uint32_t)(kb * 256);
            #pragma unroll
            for (int ks = 0; ks < 8; ks++) ldm_x4(A[ks], abase + ks * 32);
        }
        const uint32_t bufA = smb + W2_OFF + (c & 1) * W2_TILE;
        const uint32_t w2b = bufA + (uint32_t)(n0 * 272) + bfrag;
        #pragma unroll
        for (int nt = 0; nt < 8; nt++) {
            const uint32_t brow = w2b + nt * (8 * 272);
            #pragma unroll
            for (int ks2 = 0; ks2 < 4; ks2++) {
                uint32_t Bv[4];
                ldm_x4(Bv, brow + ks2 * 64);
                mma_bf16(acc[nt], A[2 * ks2],     Bv[0], Bv[1]);
                mma_bf16(acc[nt], A[2 * ks2 + 1], Bv[2], Bv[3]);
            }
        }

        if (kb == 3) {
            // all warps done reading bufA -> reuse it for h2 (bf16, stride 272)
            __syncthreads();
            #pragma unroll
            for (int nt = 0; nt < 8; nt++) {
                int col = n0 + nt * 8 + tg * 2;
                float bb0 = b2s[nb * 128 + col], bb1 = b2s[nb * 128 + col + 1];
                uint32_t lo = pack_bf16x2(fmaxf(acc[nt][0] + bb0, 0.f),
                                          fmaxf(acc[nt][1] + bb1, 0.f));
                uint32_t hi = pack_bf16x2(fmaxf(acc[nt][2] + bb0, 0.f),
                                          fmaxf(acc[nt][3] + bb1, 0.f));
                *(uint32_t*)(bp + (bufA - smb) + (m0 + g) * 272 + col * 2) = lo;
                *(uint32_t*)(bp + (bufA - smb) + (m0 + g + 8) * 272 + col * 2) = hi;
            }
            __syncthreads();

            // GEMM2(nb): rows m0..m0+15, n-half ng*32..+31
            uint32_t A2[8][4];
            {
                const uint32_t a2b = bufA + a2frag;
                #pragma unroll
                for (int ks = 0; ks < 8; ks++) ldm_x4(A2[ks], a2b + ks * 32);
            }
            #pragma unroll
            for (int nt3 = 0; nt3 < 4; nt3++) {
                const uint32_t brow = w3a + (ng * 4 + nt3) * (8 * 272);
                #pragma unroll
                for (int ks2 = 0; ks2 < 4; ks2++) {
                    uint32_t Bv[4];
                    ldm_x4(Bv, brow + ks2 * 64);
                    mma_bf16(lg[nt3], A2[2 * ks2],     Bv[0], Bv[1]);
                    mma_bf16(lg[nt3], A2[2 * ks2 + 1], Bv[2], Bv[3]);
                }
            }
        }
        __syncthreads();
    }

    // logits -> smem (f32, stride 68), reusing W2 buffer 0
    float* lbuf = (float*)(bp + LG_OFF);
    #pragma unroll
    for (int nt3 = 0; nt3 < 4; nt3++) {
        int col = ng * 32 + nt3 * 8 + tg * 2;
        lbuf[(m0 + g) * 68 + col]     = lg[nt3][0];
        lbuf[(m0 + g) * 68 + col + 1] = lg[nt3][1];
        lbuf[(m0 + g + 8) * 68 + col]     = lg[nt3][2];
        lbuf[(m0 + g + 8) * 68 + col + 1] = lg[nt3][3];
    }
    __syncthreads();

    // epilogue: 4 threads per row (quad), 128 rows
    {
        const int row = t >> 2, tq = t & 3;
        const int bsel = row >> 6, R = row & 63;
        float v[16];
        float mx = -1e30f;
        #pragma unroll
        for (int i = 0; i < 16; i++) {
            int col = i * 4 + tq;
            v[i] = lbuf[row * 68 + col] + b3s[col];
            mx = fmaxf(mx, v[i]);
        }
        mx = fmaxf(mx, __shfl_xor_sync(0xffffffffu, mx, 1));
        mx = fmaxf(mx, __shfl_xor_sync(0xffffffffu, mx, 2));

        const float* abr = ab_s + bsel * NBITS;
        float den = 0.f, num = 0.f;
        #pragma unroll
        for (int i = 0; i < 16; i++) {
            float e = expf(v[i] - mx);
            den += e;
            num = fmaf(e, abr[i * 4 + tq], num);
        }
        den += __shfl_xor_sync(0xffffffffu, den, 1);
        den += __shfl_xor_sync(0xffffffffu, den, 2);
        num += __shfl_xor_sync(0xffffffffu, num, 1);
        num += __shfl_xor_sync(0xffffffffu, num, 2);
        float pointed = num / den;

        const float* vrow = v_w1 + R * NHV;
        const float* vsr  = vs_s + bsel * NHV;
        float acc2 = 0.f;
        #pragma unroll 8
        for (int jj = 0; jj < 64; jj++) {
            int j = jj * 4 + tq;
            float vh = fmaxf(vrow[j] + vsr[j], 0.f);
            acc2 = fmaf(vh, vw2s[j], acc2);
        }
        acc2 += __shfl_xor_sync(0xffffffffu, acc2, 1);
        acc2 += __shfl_xor_sync(0xffffffffu, acc2, 2);
        if (tq == 0) {
            float vlog = acc2 + v_b2[0];
            out[(2 * pair + bsel) * NBITS + R] =
                pointed * (1.f / (1.f + expf(-vlog)));
        }
    }
}

extern "C" void kernel_launch(void* const* d_in, const int* in_sizes, int n_in,
                              void* d_out, int out_size)
{
    const float* a_bits     = (const float*)d_in[0];
    const float* shift_bits = (const float*)d_in[1];
    const float* sd_w1 = (const float*)d_in[2];
    const float* sd_b1 = (const float*)d_in[3];
    const float* sd_w2 = (const float*)d_in[4];
    const float* sd_b2 = (const float*)d_in[5];
    const float* sd_w3 = (const float*)d_in[6];
    const float* sd_b3 = (const float*)d_in[7];
    const float* ix_w1 = (const float*)d_in[8];
    const float* ix_b1 = (const float*)d_in[9];
    const float* ix_w2 = (const float*)d_in[10];
    const float* ix_b2 = (const float*)d_in[11];
    const float* ix_w3 = (const float*)d_in[12];
    const float* ix_b3 = (const float*)d_in[13];
    const float* v_w1  = (const float*)d_in[14];
    const float* v_b1  = (const float*)d_in[15];
    const float* v_w2  = (const float*)d_in[16];
    const float* v_b2  = (const float*)d_in[17];
    float* out = (float*)d_out;

    cudaFuncSetAttribute(main_mma_kernel,
                         cudaFuncAttributeMaxDynamicSharedMemorySize, SM_TOTAL);

    prep_w2_kernel<<<1024, 256>>>(ix_w2);
    prep_w3_kernel<<<128, 256>>>(ix_w3);
    shift_net_kernel<<<NB / 8, 256>>>(shift_bits, sd_w1, sd_b1, sd_w2, sd_b2,
                                      sd_w3, sd_b3, ix_w1, v_w1);
    main_mma_kernel<<<NB / 2, 512, SM_TOTAL>>>(a_bits, ix_w1, ix_b1, ix_b2, ix_b3,
                                               v_w1, v_b1, v_w2, v_b2, out);
}